// round 5
// baseline (speedup 1.0000x reference)
#include <cuda_runtime.h>
#include <cstdint>

// GaussianMixture NLL: N=65536 samples (2D), M=1024 mixtures.  SPARSITY == 0.
// nll = -sum_n log( sum_m exp(wlog_m - qf(n,m)) )
//
// v5: MIO-pressure relief. warp == mixture-quarter (TPB=128), 4 samples per
//     thread (lane-strided, coalesced) -> LDS warp-ops /4 vs v4 while keeping
//     grid=512 fully resident (~24 warps/SM). Scalar FADD accumulation after
//     ex2 removes the repack MOVs. Packed f32x2 Horner for the quadratic.

#define M_MIX   1024
#define NPAIR   (M_MIX / 2)      // 512
#define QPAIRS  (NPAIR / 4)      // 128 pairs per warp-quarter
#define TPB     128
#define SPT     4
#define SAMP_PER_BLK  128        // 32 lanes * 4 samples

__device__ float g_params[NPAIR * 12];   // pair-interleaved coefficients

typedef unsigned long long ull;

// ---------- packed f32x2 helpers ----------
__device__ __forceinline__ ull pack2(float a, float b) {
    ull r;
    unsigned int lo = __float_as_uint(a), hi = __float_as_uint(b);
    asm("mov.b64 %0, {%1, %2};" : "=l"(r) : "r"(lo), "r"(hi));
    return r;
}
__device__ __forceinline__ void unpack2(ull v, float& a, float& b) {
    unsigned int lo, hi;
    asm("mov.b64 {%0, %1}, %2;" : "=r"(lo), "=r"(hi) : "l"(v));
    a = __uint_as_float(lo);
    b = __uint_as_float(hi);
}
__device__ __forceinline__ ull fmax2_(ull a, ull b, ull c) {
    ull d; asm("fma.rn.f32x2 %0, %1, %2, %3;" : "=l"(d) : "l"(a), "l"(b), "l"(c)); return d;
}
__device__ __forceinline__ float ex2f(float x) {
    float y; asm("ex2.approx.f32 %0, %1;" : "=f"(y) : "f"(x)); return y;
}

// ---------- prep: log_softmax(w) + polynomial coefficients ----------
__global__ void gmm_prep(const float* __restrict__ mu,
                         const float* __restrict__ sigma_log,
                         const float* __restrict__ theta,
                         const float* __restrict__ w,
                         float* __restrict__ out) {
    __shared__ float red[32];
    const int m    = threadIdx.x;
    const int lane = m & 31;
    const int wid  = m >> 5;

    const float wi = w[m];

    // block max via shuffle
    float v = wi;
    #pragma unroll
    for (int o = 16; o > 0; o >>= 1) v = fmaxf(v, __shfl_xor_sync(~0u, v, o));
    if (lane == 0) red[wid] = v;
    __syncthreads();
    float wmax = red[lane & 31];
    #pragma unroll
    for (int o = 16; o > 0; o >>= 1) wmax = fmaxf(wmax, __shfl_xor_sync(~0u, wmax, o));
    wmax = __shfl_sync(~0u, wmax, 0);
    __syncthreads();

    // block sum(exp) via shuffle
    float e = __expf(wi - wmax);
    #pragma unroll
    for (int o = 16; o > 0; o >>= 1) e += __shfl_xor_sync(~0u, e, o);
    if (lane == 0) red[wid] = e;
    __syncthreads();
    float esum = red[lane & 31];
    #pragma unroll
    for (int o = 16; o > 0; o >>= 1) esum += __shfl_xor_sync(~0u, esum, o);
    esum = __shfl_sync(~0u, esum, 0);

    const float logZ = wmax + __logf(esum);

    const float sl0 = sigma_log[2 * m + 0];
    const float sl1 = sigma_log[2 * m + 1];
    const float a = __expf(-2.0f * sl0);
    const float b = __expf(-2.0f * sl1);
    float s, c;
    __sincosf(theta[m], &s, &c);

    const float g11 = a * c * c + b * s * s;
    const float g12 = (a - b) * c * s;
    const float g22 = a * s * s + b * c * c;
    const float wlog = wi - logZ - sl0 - sl1;

    const float mx = mu[2 * m + 0];
    const float my = mu[2 * m + 1];

    const float L2E = 1.4426950408889634f;

    const float c0 = -L2E * g11;
    const float c1 = -L2E * 2.0f * g12;
    const float c2 = -L2E * g22;
    const float c3 =  L2E * 2.0f * (g11 * mx + g12 * my);
    const float c4 =  L2E * 2.0f * (g12 * mx + g22 * my);
    const float c5 =  L2E * (wlog - (g11 * mx * mx + 2.0f * g12 * mx * my + g22 * my * my));

    const int j = m >> 1;
    const int l = m & 1;
    float* P = &g_params[j * 12];
    P[0  + l] = c0;
    P[2  + l] = c1;
    P[4  + l] = c2;
    P[6  + l] = c3;
    P[8  + l] = c4;
    P[10 + l] = c5;

    if (m == 0) out[0] = 0.0f;        // re-zeroed every replay -> deterministic
}

// ---------- hot loop ----------
__global__ void __launch_bounds__(TPB, 5) gmm_main(const float* __restrict__ sample,
                                                   float* __restrict__ out,
                                                   int N) {
    __shared__ __align__(16) float sp[NPAIR * 12];      // 24 KB coefficients
    __shared__ float partial[4][SAMP_PER_BLK];          // quarter partial sums
    __shared__ float warpsum[4];

    // cooperative param load (1536 float4)
    {
        const float4* gp  = (const float4*)g_params;
        float4*       sp4 = (float4*)sp;
        #pragma unroll
        for (int i = threadIdx.x; i < NPAIR * 3; i += TPB) sp4[i] = gp[i];
    }
    __syncthreads();

    const int q    = threadIdx.x >> 5;        // warp == mixture quarter (0..3)
    const int lane = threadIdx.x & 31;
    const int base = blockIdx.x * SAMP_PER_BLK;

    // per-sample packed monomials: x^2, xy, y^2, x, y
    ull xxp[SPT], xyp[SPT], yyp[SPT], xp[SPT], yp[SPT];
    float accA[SPT], accB[SPT];
    #pragma unroll
    for (int k = 0; k < SPT; ++k) {
        const int idx = base + k * 32 + lane;   // coalesced per k
        float x = 0.0f, y = 0.0f;
        if (idx < N) {
            const float2 sv = ((const float2*)sample)[idx];
            x = sv.x; y = sv.y;
        }
        const float xx = x * x, xy = x * y, yy = y * y;
        xxp[k] = pack2(xx, xx);
        xyp[k] = pack2(xy, xy);
        yyp[k] = pack2(yy, yy);
        xp[k]  = pack2(x, x);
        yp[k]  = pack2(y, y);
        accA[k] = 0.0f;
        accB[k] = 0.0f;
    }

    const float* qp = sp + q * QPAIRS * 12;

    #pragma unroll 2
    for (int j = 0; j < QPAIRS; ++j) {
        const ulonglong2* bp = (const ulonglong2*)(qp + j * 12);
        const ulonglong2 q0 = bp[0];   // {c0_pair, c1_pair}
        const ulonglong2 q1 = bp[1];   // {c2_pair, c3_pair}
        const ulonglong2 q2 = bp[2];   // {c4_pair, c5_pair}

        #pragma unroll
        for (int k = 0; k < SPT; ++k) {
            ull t = fmax2_(q2.x, yp[k],  q2.y);   // c4*y  + c5
            t     = fmax2_(q1.y, xp[k],  t);      // +c3*x
            t     = fmax2_(q1.x, yyp[k], t);      // +c2*y^2
            t     = fmax2_(q0.y, xyp[k], t);      // +c1*xy
            t     = fmax2_(q0.x, xxp[k], t);      // +c0*x^2   = L2E*(wlog-qf)
            float a0, a1;
            unpack2(t, a0, a1);
            accA[k] += ex2f(a0);                  // scalar FADD accumulate
            accB[k] += ex2f(a1);
        }
    }

    #pragma unroll
    for (int k = 0; k < SPT; ++k)
        partial[q][k * 32 + lane] = accA[k] + accB[k];
    __syncthreads();

    // combine quarters; one sample per thread
    float nll_i = 0.0f;
    const int sidx = base + threadIdx.x;
    if (sidx < N) {
        const float tot = partial[0][threadIdx.x]
                        + partial[1][threadIdx.x]
                        + partial[2][threadIdx.x]
                        + partial[3][threadIdx.x];
        nll_i = -0.69314718055994531f * __log2f(tot);
    }

    // block reduce
    #pragma unroll
    for (int o = 16; o > 0; o >>= 1)
        nll_i += __shfl_xor_sync(0xffffffffu, nll_i, o);
    if (lane == 0) warpsum[q] = nll_i;
    __syncthreads();

    if (threadIdx.x == 0) {
        atomicAdd(out, warpsum[0] + warpsum[1] + warpsum[2] + warpsum[3]);
    }
}

extern "C" void kernel_launch(void* const* d_in, const int* in_sizes, int n_in,
                              void* d_out, int out_size) {
    const float* sample    = (const float*)d_in[0];
    const float* mu        = (const float*)d_in[1];
    const float* sigma_log = (const float*)d_in[2];
    const float* theta     = (const float*)d_in[3];
    const float* w         = (const float*)d_in[4];
    float* out = (float*)d_out;

    const int N = in_sizes[0] / 2;
    const int grid = (N + SAMP_PER_BLK - 1) / SAMP_PER_BLK;

    gmm_prep<<<1, M_MIX>>>(mu, sigma_log, theta, w, out);
    gmm_main<<<grid, TPB>>>(sample, out, N);
}

// round 8
// speedup vs baseline: 1.2069x; 1.2069x over previous
#include <cuda_runtime.h>
#include <cuda_fp16.h>
#include <cstdint>

// GaussianMixture NLL: N=65536 samples (2D), M=1024 mixtures.  SPARSITY == 0.
// nll = -sum_n log( sum_m exp(wlog_m - qf(n,m)) )
//
// v6: MUFU-halving experiment. Identical structure to v5 (TPB=128,
//     warp=quarter, SPT=4) but the exponential is ex2.approx.f16x2:
//     ONE MUFU op per mixture-PAIR instead of two scalar ex2.
//     Args biased by +8 (folded into c5) so dominant fp16 terms sit near
//     magnitude ~1-4; fp16x2 chunk accumulation (8 pairs) flushed to fp32.

#define M_MIX   1024
#define NPAIR   (M_MIX / 2)      // 512
#define QPAIRS  (NPAIR / 4)      // 128 pairs per warp-quarter
#define TPB     128
#define SPT     4
#define SAMP_PER_BLK  128        // 32 lanes * 4 samples
#define BIAS    8.0f             // log2-domain bias, removed in final log

__device__ float g_params[NPAIR * 12];   // pair-interleaved coefficients

typedef unsigned long long ull;

// ---------- packed helpers ----------
__device__ __forceinline__ ull pack2(float a, float b) {
    ull r;
    unsigned int lo = __float_as_uint(a), hi = __float_as_uint(b);
    asm("mov.b64 %0, {%1, %2};" : "=l"(r) : "r"(lo), "r"(hi));
    return r;
}
__device__ __forceinline__ void unpack2(ull v, float& a, float& b) {
    unsigned int lo, hi;
    asm("mov.b64 {%0, %1}, %2;" : "=r"(lo), "=r"(hi) : "l"(v));
    a = __uint_as_float(lo);
    b = __uint_as_float(hi);
}
__device__ __forceinline__ ull fmax2_(ull a, ull b, ull c) {
    ull d; asm("fma.rn.f32x2 %0, %1, %2, %3;" : "=l"(d) : "l"(a), "l"(b), "l"(c)); return d;
}
// packed half2 ex2: one MUFU instruction, two exponentials
__device__ __forceinline__ unsigned int hex2(unsigned int x) {
    unsigned int y; asm("ex2.approx.f16x2 %0, %1;" : "=r"(y) : "r"(x)); return y;
}
__device__ __forceinline__ unsigned int hadd2u(unsigned int a, unsigned int b) {
    unsigned int y; asm("add.rn.f16x2 %0, %1, %2;" : "=r"(y) : "r"(a), "r"(b)); return y;
}
__device__ __forceinline__ unsigned int f2h2(float lo, float hi) {
    unsigned int y;
    asm("cvt.rn.f16x2.f32 %0, %1, %2;" : "=r"(y) : "f"(hi), "f"(lo));
    return y;
}

// ---------- prep: log_softmax(w) + polynomial coefficients ----------
__global__ void gmm_prep(const float* __restrict__ mu,
                         const float* __restrict__ sigma_log,
                         const float* __restrict__ theta,
                         const float* __restrict__ w,
                         float* __restrict__ out) {
    __shared__ float red[32];
    const int m    = threadIdx.x;
    const int lane = m & 31;
    const int wid  = m >> 5;

    const float wi = w[m];

    // block max via shuffle
    float v = wi;
    #pragma unroll
    for (int o = 16; o > 0; o >>= 1) v = fmaxf(v, __shfl_xor_sync(~0u, v, o));
    if (lane == 0) red[wid] = v;
    __syncthreads();
    float wmax = red[lane & 31];
    #pragma unroll
    for (int o = 16; o > 0; o >>= 1) wmax = fmaxf(wmax, __shfl_xor_sync(~0u, wmax, o));
    wmax = __shfl_sync(~0u, wmax, 0);
    __syncthreads();

    // block sum(exp) via shuffle
    float e = __expf(wi - wmax);
    #pragma unroll
    for (int o = 16; o > 0; o >>= 1) e += __shfl_xor_sync(~0u, e, o);
    if (lane == 0) red[wid] = e;
    __syncthreads();
    float esum = red[lane & 31];
    #pragma unroll
    for (int o = 16; o > 0; o >>= 1) esum += __shfl_xor_sync(~0u, esum, o);
    esum = __shfl_sync(~0u, esum, 0);

    const float logZ = wmax + __logf(esum);

    const float sl0 = sigma_log[2 * m + 0];
    const float sl1 = sigma_log[2 * m + 1];
    const float a = __expf(-2.0f * sl0);
    const float b = __expf(-2.0f * sl1);
    float s, c;
    __sincosf(theta[m], &s, &c);

    const float g11 = a * c * c + b * s * s;
    const float g12 = (a - b) * c * s;
    const float g22 = a * s * s + b * c * c;
    const float wlog = wi - logZ - sl0 - sl1;

    const float mx = mu[2 * m + 0];
    const float my = mu[2 * m + 1];

    const float L2E = 1.4426950408889634f;

    const float c0 = -L2E * g11;
    const float c1 = -L2E * 2.0f * g12;
    const float c2 = -L2E * g22;
    const float c3 =  L2E * 2.0f * (g11 * mx + g12 * my);
    const float c4 =  L2E * 2.0f * (g12 * mx + g22 * my);
    const float c5 =  L2E * (wlog - (g11 * mx * mx + 2.0f * g12 * mx * my + g22 * my * my))
                   + BIAS;   // fp16-range bias, removed in final log

    const int j = m >> 1;
    const int l = m & 1;
    float* P = &g_params[j * 12];
    P[0  + l] = c0;
    P[2  + l] = c1;
    P[4  + l] = c2;
    P[6  + l] = c3;
    P[8  + l] = c4;
    P[10 + l] = c5;

    if (m == 0) out[0] = 0.0f;        // re-zeroed every replay -> deterministic
}

// ---------- hot loop ----------
__global__ void __launch_bounds__(TPB, 5) gmm_main(const float* __restrict__ sample,
                                                   float* __restrict__ out,
                                                   int N) {
    __shared__ __align__(16) float sp[NPAIR * 12];      // 24 KB coefficients
    __shared__ float partial[4][SAMP_PER_BLK];          // quarter partial sums
    __shared__ float warpsum[4];

    // cooperative param load (1536 float4)
    {
        const float4* gp  = (const float4*)g_params;
        float4*       sp4 = (float4*)sp;
        #pragma unroll
        for (int i = threadIdx.x; i < NPAIR * 3; i += TPB) sp4[i] = gp[i];
    }
    __syncthreads();

    const int q    = threadIdx.x >> 5;        // warp == mixture quarter (0..3)
    const int lane = threadIdx.x & 31;
    const int base = blockIdx.x * SAMP_PER_BLK;

    // per-sample packed monomials: x^2, xy, y^2, x, y
    ull xxp[SPT], xyp[SPT], yyp[SPT], xp[SPT], yp[SPT];
    float accF[SPT];
    #pragma unroll
    for (int k = 0; k < SPT; ++k) {
        const int idx = base + k * 32 + lane;   // coalesced per k
        float x = 0.0f, y = 0.0f;
        if (idx < N) {
            const float2 sv = ((const float2*)sample)[idx];
            x = sv.x; y = sv.y;
        }
        const float xx = x * x, xy = x * y, yy = y * y;
        xxp[k] = pack2(xx, xx);
        xyp[k] = pack2(xy, xy);
        yyp[k] = pack2(yy, yy);
        xp[k]  = pack2(x, x);
        yp[k]  = pack2(y, y);
        accF[k] = 0.0f;
    }

    const float* qp = sp + q * QPAIRS * 12;

    // 16 chunks of 8 pairs; fp16x2 accumulate within a chunk, fp32 flush after
    for (int jc = 0; jc < QPAIRS; jc += 8) {
        unsigned int acch[SPT];
        #pragma unroll
        for (int k = 0; k < SPT; ++k) acch[k] = 0u;   // half2(0,0)

        #pragma unroll
        for (int jj = 0; jj < 8; ++jj) {
            const ulonglong2* bp = (const ulonglong2*)(qp + (jc + jj) * 12);
            const ulonglong2 q0 = bp[0];   // {c0_pair, c1_pair}
            const ulonglong2 q1 = bp[1];   // {c2_pair, c3_pair}
            const ulonglong2 q2 = bp[2];   // {c4_pair, c5_pair}

            #pragma unroll
            for (int k = 0; k < SPT; ++k) {
                ull t = fmax2_(q2.x, yp[k],  q2.y);   // c4*y  + c5(+BIAS)
                t     = fmax2_(q1.y, xp[k],  t);      // +c3*x
                t     = fmax2_(q1.x, yyp[k], t);      // +c2*y^2
                t     = fmax2_(q0.y, xyp[k], t);      // +c1*xy
                t     = fmax2_(q0.x, xxp[k], t);      // +c0*x^2
                float a0, a1;
                unpack2(t, a0, a1);
                acch[k] = hadd2u(acch[k], hex2(f2h2(a0, a1)));
            }
        }

        #pragma unroll
        for (int k = 0; k < SPT; ++k) {
            const __half2 h = *(__half2*)&acch[k];
            const float2  f = __half22float2(h);
            accF[k] += f.x + f.y;
        }
    }

    #pragma unroll
    for (int k = 0; k < SPT; ++k)
        partial[q][k * 32 + lane] = accF[k];
    __syncthreads();

    // combine quarters; one sample per thread
    float nll_i = 0.0f;
    const int sidx = base + threadIdx.x;
    if (sidx < N) {
        const float tot = partial[0][threadIdx.x]
                        + partial[1][threadIdx.x]
                        + partial[2][threadIdx.x]
                        + partial[3][threadIdx.x];
        // tot = 2^BIAS * true_sum  ->  ll*log2e = log2(tot) - BIAS
        nll_i = 0.69314718055994531f * (BIAS - __log2f(tot));
    }

    // block reduce
    #pragma unroll
    for (int o = 16; o > 0; o >>= 1)
        nll_i += __shfl_xor_sync(0xffffffffu, nll_i, o);
    if (lane == 0) warpsum[q] = nll_i;
    __syncthreads();

    if (threadIdx.x == 0) {
        atomicAdd(out, warpsum[0] + warpsum[1] + warpsum[2] + warpsum[3]);
    }
}

extern "C" void kernel_launch(void* const* d_in, const int* in_sizes, int n_in,
                              void* d_out, int out_size) {
    const float* sample    = (const float*)d_in[0];
    const float* mu        = (const float*)d_in[1];
    const float* sigma_log = (const float*)d_in[2];
    const float* theta     = (const float*)d_in[3];
    const float* w         = (const float*)d_in[4];
    float* out = (float*)d_out;

    const int N = in_sizes[0] / 2;
    const int grid = (N + SAMP_PER_BLK - 1) / SAMP_PER_BLK;

    gmm_prep<<<1, M_MIX>>>(mu, sigma_log, theta, w, out);
    gmm_main<<<grid, TPB>>>(sample, out, N);
}